// round 1
// baseline (speedup 1.0000x reference)
#include <cuda_runtime.h>
#include <math.h>

#define BB 4
#define C 64
#define C2 128
#define H 128
#define W 128
#define HW (H*W)
#define FIELD_N (BB*C*HW)
#define TILE_H 8
#define TILE_W 16
#define NPIX 128
#define NTHREADS 256
#define MAX_STEPS 50
#define DT_C 0.1f
#define THRESH_C 0.01

// smem layout offsets (in floats)
#define OFF_W1 0            // 128*64
#define OFF_W2 8192         // 64*128
#define OFF_H  16384        // 128*128
#define OFF_F  32768        // 64*10*18
#define OFF_DW 44288        // 64*9
#define OFF_B1 44864        // 128
#define OFF_B2 44992        // 64
#define OFF_DB 45056        // 64
#define OFF_RED 45120       // 8
#define SMEM_FLOATS 45128
#define SMEM_BYTES (SMEM_FLOATS * 4)

__device__ float g_buf0[FIELD_N];
__device__ float g_buf1[FIELD_N];
__device__ int    g_done;
__device__ int    g_steps;
__device__ int    g_cur;
__device__ double g_sum;

__global__ void afe_init_kernel(const float* __restrict__ field) {
    int tid = blockIdx.x * blockDim.x + threadIdx.x;
    if (tid == 0) { g_done = 0; g_steps = 0; g_cur = 0; g_sum = 0.0; }
    int stride = gridDim.x * blockDim.x;
    for (int i = tid; i < FIELD_N; i += stride) g_buf0[i] = field[i];
}

__global__ __launch_bounds__(NTHREADS, 1)
void afe_step_kernel(const float* __restrict__ dw, const float* __restrict__ db,
                     const float* __restrict__ w1, const float* __restrict__ b1,
                     const float* __restrict__ w2, const float* __restrict__ b2,
                     const float* __restrict__ dcoeff) {
    if (g_done) return;

    extern __shared__ float sm[];
    float* sw1 = sm + OFF_W1;   // [j*64 + c], natural w1 layout
    float* sw2 = sm + OFF_W2;   // [c*128 + j], natural w2 layout
    float* sh  = sm + OFF_H;    // [j*128 + p]
    float* sf  = sm + OFF_F;    // [c*180 + row*18 + col], halo tile
    float* sdw = sm + OFF_DW;   // [c*9 + t]
    float* sb1 = sm + OFF_B1;
    float* sb2 = sm + OFF_B2;
    float* sdb = sm + OFF_DB;
    float* sred = sm + OFF_RED;

    const float* fin  = g_cur ? g_buf1 : g_buf0;
    float*       fout = g_cur ? g_buf0 : g_buf1;

    const int b  = blockIdx.z;
    const int y0 = blockIdx.y * TILE_H;
    const int x0 = blockIdx.x * TILE_W;
    const int tid = threadIdx.x;
    const int g  = tid & 31;    // pixel lane
    const int ws = tid >> 5;    // warp sub-index 0..7

    // ---- load weights / biases (coalesced) ----
    #pragma unroll
    for (int i = tid; i < C2 * C; i += NTHREADS) sw1[i] = w1[i];
    #pragma unroll
    for (int i = tid; i < C * C2; i += NTHREADS) sw2[i] = w2[i];
    for (int i = tid; i < C * 9; i += NTHREADS) sdw[i] = dw[i];
    if (tid < C2) sb1[tid] = b1[tid];
    if (tid < C)  sb2[tid] = b2[tid];
    if (tid >= C && tid < 2 * C) sdb[tid - C] = db[tid - C];

    // ---- load f tile with halo (zero padding = SAME) ----
    for (int i = tid; i < C * 180; i += NTHREADS) {
        int c  = i / 180;
        int r  = (i % 180) / 18;
        int xx = i % 18;
        int y = y0 - 1 + r;
        int x = x0 - 1 + xx;
        float v = 0.0f;
        if (y >= 0 && y < H && x >= 0 && x < W)
            v = fin[((b * C + c) * H + y) * W + x];
        sf[i] = v;
    }
    __syncthreads();

    // ---- stage 1: h[j][p] = gelu( sum_c w1[j][c] * f[c][p] + b1[j] ) ----
    // this thread: j = ws*16 + ij (16 values), p = g + 32*k (4 pixels)
    {
        const int jbase = ws * 16;
        float acc[16][4];
        #pragma unroll
        for (int ij = 0; ij < 16; ij++) {
            float bv = sb1[jbase + ij];
            #pragma unroll
            for (int k = 0; k < 4; k++) acc[ij][k] = bv;
        }
        for (int c = 0; c < C; c++) {
            float fv[4];
            #pragma unroll
            for (int k = 0; k < 4; k++) {
                int p = g + 32 * k;
                fv[k] = sf[c * 180 + ((p >> 4) + 1) * 18 + (p & 15) + 1];
            }
            #pragma unroll
            for (int ij = 0; ij < 16; ij++) {
                float wv = sw1[(jbase + ij) * C + c];  // warp-broadcast
                #pragma unroll
                for (int k = 0; k < 4; k++)
                    acc[ij][k] = fmaf(wv, fv[k], acc[ij][k]);
            }
        }
        #pragma unroll
        for (int ij = 0; ij < 16; ij++) {
            #pragma unroll
            for (int k = 0; k < 4; k++) {
                float x = acc[ij][k];
                float gl = 0.5f * x * (1.0f + erff(x * 0.70710678118654752f));
                sh[(jbase + ij) * NPIX + g + 32 * k] = gl;
            }
        }
    }
    __syncthreads();

    // ---- stage 2: react[c][p] = sum_j w2[c][j] * h[j][p] ----
    // this thread: c = ws*8 + ic (8 values), p = g + 32*k (4 pixels)
    const int cbase = ws * 8;
    float acc2[8][4];
    #pragma unroll
    for (int ic = 0; ic < 8; ic++)
        #pragma unroll
        for (int k = 0; k < 4; k++) acc2[ic][k] = 0.0f;

    for (int j = 0; j < C2; j++) {
        float hv[4];
        #pragma unroll
        for (int k = 0; k < 4; k++) hv[k] = sh[j * NPIX + g + 32 * k];
        #pragma unroll
        for (int ic = 0; ic < 8; ic++) {
            float wv = sw2[(cbase + ic) * C2 + j];  // warp-broadcast
            #pragma unroll
            for (int k = 0; k < 4; k++)
                acc2[ic][k] = fmaf(wv, hv[k], acc2[ic][k]);
        }
    }

    // ---- depthwise + epilogue ----
    const float dc = dcoeff[0];
    float lsum = 0.0f;
    #pragma unroll
    for (int ic = 0; ic < 8; ic++) {
        const int c = cbase + ic;
        float wd[9];
        #pragma unroll
        for (int t = 0; t < 9; t++) wd[t] = sdw[c * 9 + t];
        const float bias2 = sb2[c];
        const float dbv = sdb[c];
        #pragma unroll
        for (int k = 0; k < 4; k++) {
            int p = g + 32 * k;
            int r = p >> 4, col = p & 15;
            const float* base = sf + c * 180;
            float s = 0.0f;
            #pragma unroll
            for (int dy = 0; dy < 3; dy++) {
                #pragma unroll
                for (int dx = 0; dx < 3; dx++) {
                    s = fmaf(wd[dy * 3 + dx], base[(r + dy) * 18 + col + dx], s);
                }
            }
            float react = acc2[ic][k] + bias2;
            float deriv = dc * (s + dbv) + react;
            float fold = base[(r + 1) * 18 + col + 1];
            float fnew = fmaf(DT_C, deriv, fold);
            lsum += fabsf(fnew - fold);
            fout[((b * C + c) * H + (y0 + r)) * W + (x0 + col)] = fnew;
        }
    }

    // ---- block reduce |delta| and accumulate globally ----
    #pragma unroll
    for (int off = 16; off > 0; off >>= 1)
        lsum += __shfl_xor_sync(0xFFFFFFFFu, lsum, off);
    if (g == 0) sred[ws] = lsum;
    __syncthreads();
    if (tid == 0) {
        float bs = 0.0f;
        #pragma unroll
        for (int i = 0; i < 8; i++) bs += sred[i];
        atomicAdd(&g_sum, (double)bs);
    }
}

__global__ void afe_finalize_kernel() {
    if (!g_done) {
        double mean = g_sum / (double)FIELD_N;
        g_steps += 1;
        if (mean < THRESH_C) g_done = 1;
        g_cur ^= 1;
    }
    g_sum = 0.0;
}

__global__ void afe_output_kernel(float* __restrict__ out, int out_size) {
    const float* f = g_cur ? g_buf1 : g_buf0;
    int tid = blockIdx.x * blockDim.x + threadIdx.x;
    int stride = gridDim.x * blockDim.x;
    float stepsf = (float)g_steps;
    for (int i = tid; i < out_size; i += stride)
        out[i] = (i < FIELD_N) ? f[i] : stepsf;
}

extern "C" void kernel_launch(void* const* d_in, const int* in_sizes, int n_in,
                              void* d_out, int out_size) {
    const float* field  = (const float*)d_in[0];
    const float* dw     = (const float*)d_in[1];
    const float* db     = (const float*)d_in[2];
    const float* w1     = (const float*)d_in[3];
    const float* b1     = (const float*)d_in[4];
    const float* w2     = (const float*)d_in[5];
    const float* b2     = (const float*)d_in[6];
    const float* dcoeff = (const float*)d_in[7];

    cudaFuncSetAttribute(afe_step_kernel,
                         cudaFuncAttributeMaxDynamicSharedMemorySize, SMEM_BYTES);

    afe_init_kernel<<<1024, 256>>>(field);

    dim3 grid(W / TILE_W, H / TILE_H, BB);  // (8, 16, 4)
    for (int s = 0; s < MAX_STEPS; s++) {
        afe_step_kernel<<<grid, NTHREADS, SMEM_BYTES>>>(dw, db, w1, b1, w2, b2, dcoeff);
        afe_finalize_kernel<<<1, 1>>>();
    }

    afe_output_kernel<<<2048, 256>>>((float*)d_out, out_size);
}